// round 16
// baseline (speedup 1.0000x reference)
#include <cuda_runtime.h>
#include <cstdint>

#define B          64
#define CROP       64
#define MAXN       196
#define KNBR       6
#define NSCORE     (3*CROP*CROP)        // 12288
#define WB         247
#define WS         18
#define TB         256                  // conv kernel threads
#define TC         1024                 // select kernel threads
#define TN         512                  // nn kernel threads (16 warps)
#define NIT        (NSCORE/TC)          // 12
#define NWARP      (TC/32)              // 32
#define GPITCH     72                   // padded gray pitch (64 + 2*4)

typedef unsigned long long ull;

// output layout (f32, concatenated flattened tuple)
#define O_NODES 0
#define O_EI    62720
#define O_EF    213248
#define O_BI    439040
#define O_NV    451584
#define O_EV    464128
#define N_EDGE_TOT 75264                // B*196*6

__device__ __align__(16) float g_resp[B * NSCORE];   // 3 MB scratch
__device__ float2 g_xy [B * MAXN];
__device__ int    g_val[B * MAXN];

__device__ __forceinline__ float score_of(float r) {
    float m = fabsf(r);
    return (m > 0.1f) ? m : -1.0f;
}
__device__ __forceinline__ unsigned enc_f(float s) {
    unsigned b = __float_as_uint(s);
    return (b & 0x80000000u) ? ~b : (b | 0x80000000u);
}

// 4 consecutive outputs (one row) of a KxK SAME conv on the zero-padded gray.
// s_gpad MUST be 16B-aligned: float4 loads at (row*72 + x0)*4 bytes
// (72*4=288 and x0*4 both multiples of 16).
template<int K, int PAD, int WOFF>
__device__ __forceinline__ float4 conv_quad(const float* __restrict__ s_gpad,
                                            const float* __restrict__ s_w,
                                            int y, int x0)
{
    float a0 = 0.f, a1 = 0.f, a2 = 0.f, a3 = 0.f;
    #pragma unroll
    for (int dy = 0; dy < K; dy++) {
        const float4* gr4 = reinterpret_cast<const float4*>(
            s_gpad + (y + dy - PAD + 4)*GPITCH + x0);
        float4 q0 = gr4[0], q1 = gr4[1], q2 = gr4[2];
        float gv[12] = {q0.x,q0.y,q0.z,q0.w, q1.x,q1.y,q1.z,q1.w,
                        q2.x,q2.y,q2.z,q2.w};
        const float* wr = s_w + WOFF + dy*K;
        #pragma unroll
        for (int dx = 0; dx < K; dx++) {
            float w = wr[dx];
            const int o = 4 - PAD + dx;
            a0 = fmaf(gv[o],     w, a0);
            a1 = fmaf(gv[o + 1], w, a1);
            a2 = fmaf(gv[o + 2], w, a2);
            a3 = fmaf(gv[o + 3], w, a3);
        }
    }
    return make_float4(a0, a1, a2, a3);
}

// ============================================================
// Kernel 1: crop + gray + DoG conv.  grid = (64, 12) = (batch, ch*4 + quarter)
// Each block: one channel, 16 output rows, 256 threads x one 4-wide quad.
// ============================================================
__global__ void __launch_bounds__(TB)
conv_kernel(const float* __restrict__ img,
            const float* __restrict__ w1,
            const float* __restrict__ w2,
            const float* __restrict__ w3)
{
    __shared__ alignas(16) float s_gpad[GPITCH*GPITCH];  // 16B-aligned, first
    __shared__ float s_win[3*WS*WS];
    __shared__ float s_w[115];

    const int b  = blockIdx.x;
    const int s  = blockIdx.y;
    const int ch = s >> 2;
    const int q  = s & 3;
    const int t  = threadIdx.x;
    const float REC3 = __uint_as_float(0x3EAAAAABu);  // f32(1/3)

    const int pad = (ch == 0) ? 1 : (ch == 1) ? 2 : 4;
    const int rlo = max(0, q*16 - pad);
    const int rhi = min(63, q*16 + 15 + pad);

    if (t < 9)  s_w[t]      = w1[t];
    if (t < 25) s_w[9 + t]  = w2[t];
    if (t < 81) s_w[34 + t] = w3[t];
    for (int i = t; i < 3*WS*WS; i += TB) {
        int c = i / (WS*WS);
        int r = (i % (WS*WS)) / WS;
        int x = i % WS;
        s_win[i] = img[(((size_t)b*3 + c)*512 + (WB + r))*512 + (WB + x)];
    }
    for (int i = t; i < GPITCH*GPITCH; i += TB) s_gpad[i] = 0.0f;
    __syncthreads();

    // crop (bilinear) + gray mean — only rows this slice needs
    for (int p = rlo*64 + t; p < (rhi + 1)*64; p += TB) {
        int iy = p >> 6, ix = p & 63;
        float bx = __fsub_rn(__fmul_rn((float)ix + 0.5f, 0.03125f), 1.0f);
        float by = __fsub_rn(__fmul_rn((float)iy + 0.5f, 0.03125f), 1.0f);
        float px = __fsub_rn(__fmul_rn(__fadd_rn(__fmul_rn(bx, 0.03125f), 1.0f), 256.0f), 0.5f);
        float py = __fsub_rn(__fmul_rn(__fadd_rn(__fmul_rn(by, 0.03125f), 1.0f), 256.0f), 0.5f);
        int ix0 = (int)floorf(px), iy0 = (int)floorf(py);
        float fx = __fsub_rn(px, (float)ix0);
        float fy = __fsub_rn(py, (float)iy0);
        float wx0 = __fsub_rn(1.0f, fx);
        float wy0 = __fsub_rn(1.0f, fy);
        int lx0 = ix0 - WB, ly0 = iy0 - WB;
        float sum = 0.0f;
        #pragma unroll
        for (int c = 0; c < 3; c++) {
            const float* wc = s_win + c*WS*WS;
            float v00 = wc[ly0*WS + lx0],     v01 = wc[ly0*WS + lx0 + 1];
            float v10 = wc[(ly0+1)*WS + lx0], v11 = wc[(ly0+1)*WS + lx0 + 1];
            float tx0 = __fadd_rn(__fmul_rn(v00, wx0), __fmul_rn(v01, fx));
            float tx1 = __fadd_rn(__fmul_rn(v10, wx0), __fmul_rn(v11, fx));
            float v   = __fadd_rn(__fmul_rn(tx0, wy0), __fmul_rn(tx1, fy));
            sum = __fadd_rn(sum, v);
        }
        s_gpad[(iy + 4)*GPITCH + ix + 4] = __fmul_rn(sum, REC3);
    }
    __syncthreads();

    const int y  = q*16 + (t >> 4);
    const int x0 = (t & 15) * 4;
    float4 r;
    if (ch == 0)      r = conv_quad<3, 1, 0 >(s_gpad, s_w, y, x0);
    else if (ch == 1) r = conv_quad<5, 2, 9 >(s_gpad, s_w, y, x0);
    else              r = conv_quad<9, 4, 34>(s_gpad, s_w, y, x0);
    reinterpret_cast<float4*>(g_resp + (size_t)b*NSCORE + ch*4096)[q*256 + t] = r;
}

// smem layout offsets (bytes) for select_kernel (all 16B-aligned)
#define SM_SEL    0        // 256 ull
#define SM_WHIST  2048     // 32*256 u32
#define SM_PART   34816    // 1024 int
#define SM_SCAN   38912    // 385 int
#define SM_WC     40464    // 384 int
#define SM_WS     42000    // 32 int
#define SM_TOTAL  42128

// ============================================================
// Kernel 2: top-k select + sort + node outputs.  grid = 64
// ============================================================
__global__ void __launch_bounds__(TC, 1)
select_kernel(float* __restrict__ out)
{
    extern __shared__ unsigned char dsm[];
    ull*      s_sel   = (ull*)(dsm + SM_SEL);
    unsigned* s_whist = (unsigned*)(dsm + SM_WHIST);
    int*      s_part  = (int*)(dsm + SM_PART);
    int*      s_scan  = (int*)(dsm + SM_SCAN);
    int*      s_wc    = (int*)(dsm + SM_WC);
    int*      s_ws    = (int*)(dsm + SM_WS);
    __shared__ unsigned s_pref;
    __shared__ int s_rem, s_tot;

    const int b = blockIdx.x;
    const int t = threadIdx.x;
    const int lane = t & 31, warp = t >> 5;

    // ---- encode keys straight from global (coalesced, L2-hot) ----
    const float* resp = g_resp + (size_t)b*NSCORE;
    unsigned u[NIT];
    #pragma unroll
    for (int it = 0; it < NIT; it++)
        u[it] = enc_f(score_of(resp[it*TC + t]));
    if (t == 0) { s_pref = 0; s_rem = MAXN; }
    __syncthreads();

    // ---- radix select with early exit, zero atomics ----
    int sh = -1;
    for (int pass = 0; pass < 4; pass++) {
        const int shift = 24 - 8*pass;
        {
            uint4* wz = (uint4*)s_whist;
            wz[t]        = make_uint4(0,0,0,0);
            wz[TC + t]   = make_uint4(0,0,0,0);
        }
        __syncthreads();
        const unsigned pref = s_pref;
        const int rem = s_rem;
        unsigned* wh = s_whist + warp*256;
        #pragma unroll
        for (int it = 0; it < NIT; it++) {
            unsigned uu = u[it];
            bool ok = (pass == 0) || ((uu >> (shift + 8)) == (pref >> (shift + 8)));
            unsigned active = __ballot_sync(0xffffffffu, ok);
            if (ok) {
                unsigned bin = (uu >> shift) & 255u;
                unsigned mset = __match_any_sync(active, bin);
                if (lane == __ffs(mset) - 1)
                    wh[bin] += __popc(mset);
            }
        }
        __syncthreads();
        {
            int bin = t & 255, grp = t >> 8;
            int v = 0;
            #pragma unroll
            for (int w = 0; w < 8; w++)
                v += (int)s_whist[(grp*8 + w)*256 + bin];
            s_part[grp*256 + bin] = v;
        }
        __syncthreads();
        int v = 0;
        if (t < 256) {
            v = s_part[t] + s_part[256 + t] + s_part[512 + t] + s_part[768 + t];
            #pragma unroll
            for (int off = 1; off < 32; off <<= 1) {
                int o = __shfl_down_sync(0xffffffffu, v, off);
                if (lane + off < 32) v += o;
            }
            if (lane == 0) s_ws[warp] = v;
        }
        __syncthreads();
        if (t < 8) {
            int wv = s_ws[t];
            #pragma unroll
            for (int off = 1; off < 8; off <<= 1) {
                int o = __shfl_down_sync(0xFFu, wv, off);
                if (t + off < 8) wv += o;
            }
            s_ws[t] = wv;
        }
        __syncthreads();
        if (t < 256)
            s_scan[t] = v + ((warp < 7) ? s_ws[warp + 1] : 0);   // suffix sums
        __syncthreads();
        if (t < 256) {
            int Sd  = s_scan[t];
            int Sd1 = (t == 255) ? 0 : s_scan[t + 1];
            if (Sd >= rem && Sd1 < rem) {          // unique crossing thread
                s_pref = pref | ((unsigned)t << shift);
                s_rem  = rem - Sd1;
                s_tot  = (MAXN - rem) + Sd;        // all candidates >= boundary
            }
        }
        __syncthreads();
        if (s_tot <= 256) { sh = shift; break; }
    }

    if (sh >= 0) {
        // ---- PATH A: collect all candidates >= truncated boundary, sort ----
        const unsigned th = s_pref >> sh;
        const int tot = s_tot;
        #pragma unroll
        for (int it = 0; it < NIT; it++) {
            unsigned bal = __ballot_sync(0xffffffffu, (u[it] >> sh) >= th);
            if (lane == 0) s_wc[it*NWARP + warp] = __popc(bal);
        }
        __syncthreads();
        if (t < 384) {
            int v = s_wc[t];
            #pragma unroll
            for (int off = 1; off < 32; off <<= 1) {
                int o = __shfl_up_sync(0xffffffffu, v, off);
                if (lane >= off) v += o;
            }
            s_scan[t] = v;
            if (lane == 31) s_ws[warp] = v;
        }
        __syncthreads();
        if (t < 12) {
            int wv = s_ws[t];
            #pragma unroll
            for (int off = 1; off < 16; off <<= 1) {
                int o = __shfl_up_sync(0xFFFu, wv, off);
                if (t >= off) wv += o;
            }
            s_ws[t] = wv;
        }
        __syncthreads();
        #pragma unroll
        for (int it = 0; it < NIT; it++) {
            bool pred = (u[it] >> sh) >= th;
            unsigned bal = __ballot_sync(0xffffffffu, pred);
            int cw = it*NWARP + warp;
            int widx = cw >> 5;
            int excl = s_scan[cw] + ((widx > 0) ? s_ws[widx - 1] : 0) - __popc(bal);
            if (pred) {
                int rank = excl + __popc(bal & ((1u << lane) - 1u));
                s_sel[rank] = (((ull)u[it]) << 32) | (unsigned)(~(unsigned)(it*TC + t));
            }
        }
        if (t >= tot && t < 256) s_sel[t] = 0ULL;
        __syncthreads();
    } else {
        // ---- PATH B (fallback): exact threshold + ordered tie collection ----
        const unsigned u_t = s_pref;
        const int ktie = s_rem;
        #pragma unroll
        for (int it = 0; it < NIT; it++) {
            unsigned bg = __ballot_sync(0xffffffffu, u[it] > u_t);
            unsigned bt = __ballot_sync(0xffffffffu, u[it] == u_t);
            if (lane == 0) s_wc[it*NWARP + warp] = (__popc(bg) << 16) | __popc(bt);
        }
        __syncthreads();
        if (t < 384) {
            int v = s_wc[t];
            #pragma unroll
            for (int off = 1; off < 32; off <<= 1) {
                int o = __shfl_up_sync(0xffffffffu, v, off);
                if (lane >= off) v += o;
            }
            s_scan[t] = v;
            if (lane == 31) s_ws[warp] = v;
        }
        __syncthreads();
        if (t < 12) {
            int wv = s_ws[t];
            #pragma unroll
            for (int off = 1; off < 16; off <<= 1) {
                int o = __shfl_up_sync(0xFFFu, wv, off);
                if (t >= off) wv += o;
            }
            s_ws[t] = wv;
        }
        __syncthreads();
        const int cG = s_ws[11] >> 16;
        #pragma unroll
        for (int it = 0; it < NIT; it++) {
            unsigned uu = u[it];
            bool g = (uu > u_t), e = (uu == u_t);
            unsigned bg = __ballot_sync(0xffffffffu, g);
            unsigned bt = __ballot_sync(0xffffffffu, e);
            int cw = it*NWARP + warp;
            int widx = cw >> 5;
            int incl = s_scan[cw] + ((widx > 0) ? s_ws[widx - 1] : 0);
            int excl = incl - ((__popc(bg) << 16) | __popc(bt));
            unsigned below = (1u << lane) - 1u;
            if (g) {
                int rank = (excl >> 16) + __popc(bg & below);
                s_sel[rank] = (((ull)uu) << 32) | (unsigned)(~(unsigned)(it*TC + t));
            }
            if (e) {
                int rank = (excl & 0xFFFF) + __popc(bt & below);
                if (rank < ktie)
                    s_sel[cG + rank] = (((ull)u_t) << 32) | (unsigned)(~(unsigned)(it*TC + t));
            }
        }
        if (t >= MAXN && t < 256) s_sel[t] = 0ULL;
        __syncthreads();
    }

    // ---- bitonic sort 256 keys descending (value desc, index asc) ----
    ull k = (t < 256) ? s_sel[t] : 0ULL;
    if (t < 256) {
        #pragma unroll
        for (int kk = 2; kk <= 32; kk <<= 1) {
            #pragma unroll
            for (int j = kk >> 1; j > 0; j >>= 1) {
                ull o = __shfl_xor_sync(0xffffffffu, k, j);
                bool takeMax = (((t & kk) == 0) != ((t & j) != 0));
                k = takeMax ? (k > o ? k : o) : (k < o ? k : o);
            }
        }
    }
    #pragma unroll
    for (int kk = 64; kk <= 256; kk <<= 1) {
        for (int j = kk >> 1; j >= 32; j >>= 1) {
            __syncthreads();
            if (t < 256) s_sel[t] = k;
            __syncthreads();
            if (t < 256) {
                ull o = s_sel[t ^ j];
                bool takeMax = (((t & kk) == 0) != ((t & j) != 0));
                k = takeMax ? (k > o ? k : o) : (k < o ? k : o);
            }
        }
        if (t < 256) {
            #pragma unroll
            for (int j = 16; j > 0; j >>= 1) {
                ull o = __shfl_xor_sync(0xffffffffu, k, j);
                bool takeMax = (((t & kk) == 0) != ((t & j) != 0));
                k = takeMax ? (k > o ? k : o) : (k < o ? k : o);
            }
        }
    }

    // ---- node features + export (x, y, valid) for the NN kernel ----
    const float REC63x2 = __uint_as_float(0x3D020821u);  // f32(1/63)*2
    if (t < MAXN) {
        unsigned idx = ~((unsigned)k);
        float rv = resp[idx];
        bool valid = (fabsf(rv) > 0.1f);
        int c  = idx >> 12;
        int rem2 = idx & 4095;
        int yi = rem2 >> 6, xi = rem2 & 63;
        float xc = __fsub_rn(__fmul_rn((float)xi, REC63x2), 1.0f);
        float yc = __fsub_rn(__fmul_rn((float)yi, REC63x2), 1.0f);
        float ecc = __fsqrt_rn(__fadd_rn(__fmul_rn(xc, xc), __fmul_rn(yc, yc)));
        float pol = (rv > 0.0f) ? 1.0f : ((rv < 0.0f) ? -1.0f : 0.0f);
        float vf = valid ? 1.0f : 0.0f;
        float* nrow = out + O_NODES + ((size_t)b*MAXN + t)*5;
        nrow[0] = xc * vf;
        nrow[1] = yc * vf;
        nrow[2] = pol * vf;
        nrow[3] = (float)c * vf;
        nrow[4] = ecc * vf;
        g_xy [b*MAXN + t] = make_float2(xc * vf, yc * vf);
        g_val[b*MAXN + t] = valid ? 1 : 0;
        out[O_NV + b*MAXN + t] = vf;
        out[O_BI + b*MAXN + t] = (float)b;
    }
}

// ============================================================
// Kernel 3: 6-NN + edges, one warp per node.  grid = (64, 13), 512 thr
// ============================================================
__global__ void __launch_bounds__(TN)
nn_kernel(float* __restrict__ out)
{
    __shared__ float2 s_xy[MAXN];
    __shared__ int s_val[MAXN];

    const int b = blockIdx.x;
    const int t = threadIdx.x;
    const int lane = t & 31, warp = t >> 5;

    if (t < MAXN) {
        int v = g_val[b*MAXN + t];
        float2 xy = g_xy[b*MAXN + t];
        s_val[t] = v;
        // sentinel coords for invalid nodes: distance becomes inf, sorts after
        // all real distances (like the reference's 1e9); those slots only ever
        // emit ev=0 -> all-zero outputs.
        s_xy[t] = v ? xy : make_float2(1e19f, 1e19f);
    }
    __syncthreads();

    const int node = blockIdx.y * (TN/32) + warp;
    if (node >= MAXN) return;

    const float2 p = s_xy[node];
    const int sv = s_val[node];

    // collect 7 raw keys; m=0..5 always in-range (lane+160 <= 191 < 196)
    ull key[7];
    #pragma unroll
    for (int m = 0; m < 6; m++) {
        int j = lane + m*32;
        float2 pj = s_xy[j];
        float dx = __fsub_rn(p.x, pj.x);
        float dy = __fsub_rn(p.y, pj.y);
        float s2 = __fadd_rn(__fmul_rn(dx, dx), __fmul_rn(dy, dy));
        float d = (s2 > 0.0f) ? __fsqrt_rn(s2) : 0.0f;
        if (j == node) d = 1000000000.0f;
        key[m] = (((ull)__float_as_uint(d)) << 32) | (unsigned)j;
    }
    {
        int j = lane + 192;
        if (j < MAXN) {
            float2 pj = s_xy[j];
            float dx = __fsub_rn(p.x, pj.x);
            float dy = __fsub_rn(p.y, pj.y);
            float s2 = __fadd_rn(__fmul_rn(dx, dx), __fmul_rn(dy, dy));
            float d = (s2 > 0.0f) ? __fsqrt_rn(s2) : 0.0f;
            if (j == node) d = 1000000000.0f;
            key[6] = (((ull)__float_as_uint(d)) << 32) | (unsigned)j;
        } else {
            key[6] = 0xFFFFFFFF00000000ULL;   // sorts after everything real
        }
    }

    // odd-even transposition sort of 7 keys (21 CAS)
    #pragma unroll
    for (int r = 0; r < 7; r++) {
        #pragma unroll
        for (int i = (r & 1); i + 1 < 7; i += 2) {
            ull a = key[i], c = key[i+1];
            key[i]   = (a < c) ? a : c;
            key[i+1] = (a < c) ? c : a;
        }
    }

    // 6-round tournament, 32-bit reductions (d >= 0 -> bits monotone unsigned)
    unsigned res_d = 0xFFFFFFFFu, res_j = 0;
    #pragma unroll
    for (int q = 0; q < KNBR; q++) {
        unsigned dh = (unsigned)(key[0] >> 32);
        unsigned jh = (unsigned)key[0];
        unsigned dmin = dh;
        #pragma unroll
        for (int off = 16; off > 0; off >>= 1) {
            unsigned o = __shfl_xor_sync(0xffffffffu, dmin, off);
            dmin = (o < dmin) ? o : dmin;
        }
        unsigned jm = (dh == dmin) ? jh : 0xFFFFFFFFu;
        #pragma unroll
        for (int off = 16; off > 0; off >>= 1) {
            unsigned o = __shfl_xor_sync(0xffffffffu, jm, off);
            jm = (o < jm) ? o : jm;
        }
        if (lane == q) { res_d = dmin; res_j = jm; }
        if (dh == dmin && jh == jm) {
            #pragma unroll
            for (int r = 0; r < 6; r++) key[r] = key[r+1];
            key[6] = 0xFFFFFFFFFFFFFFFFULL;
        }
    }

    // lanes 0..5 emit edges (select-masked: sentinel values never leak)
    if (lane < KNBR) {
        const float DIST_T = (float)(4.05 / 4.2);
        unsigned jd = res_j;
        float d = __uint_as_float(res_d);
        bool ev = (d < DIST_T) && (sv != 0);
        float2 pj = s_xy[jd];
        float dx = __fsub_rn(pj.x, p.x);
        float dy = __fsub_rn(pj.y, p.y);
        float s2 = __fadd_rn(__fmul_rn(dx, dx), __fmul_rn(dy, dy));
        float cd = (s2 > 0.0f) ? __fsqrt_rn(s2) : 0.0f;
        size_t e = ((size_t)b*MAXN + node)*KNBR + lane;
        out[O_EI + e]              = ev ? (float)(b*MAXN + node) : 0.0f;
        out[O_EI + N_EDGE_TOT + e] = ev ? (float)(b*MAXN + jd)   : 0.0f;
        out[O_EF + e*3 + 0] = ev ? dx : 0.0f;
        out[O_EF + e*3 + 1] = ev ? dy : 0.0f;
        out[O_EF + e*3 + 2] = ev ? cd : 0.0f;
        out[O_EV + e] = ev ? 1.0f : 0.0f;
    }
}

extern "C" void kernel_launch(void* const* d_in, const int* in_sizes, int n_in,
                              void* d_out, int out_size)
{
    const float* img = (const float*)d_in[0];
    const float* w1  = (const float*)d_in[1];
    const float* w2  = (const float*)d_in[2];
    const float* w3  = (const float*)d_in[3];
    float* out = (float*)d_out;

    conv_kernel<<<dim3(B, 12), TB>>>(img, w1, w2, w3);

    cudaFuncSetAttribute(select_kernel,
                         cudaFuncAttributeMaxDynamicSharedMemorySize, SM_TOTAL);
    select_kernel<<<B, TC, SM_TOTAL>>>(out);

    nn_kernel<<<dim3(B, (MAXN + TN/32 - 1) / (TN/32)), TN>>>(out);
}

// round 17
// speedup vs baseline: 1.0058x; 1.0058x over previous
#include <cuda_runtime.h>
#include <cstdint>

#define B          64
#define CROP       64
#define MAXN       196
#define KNBR       6
#define NSCORE     (3*CROP*CROP)        // 12288
#define WB         247
#define WS         18
#define TB         256                  // crop/conv kernel threads
#define TC         1024                 // select kernel threads
#define TN         512                  // nn kernel threads (16 warps)
#define NIT        (NSCORE/TC)          // 12
#define NWARP      (TC/32)              // 32
#define GPITCH     72                   // padded gray pitch (64 + 2*4)
#define GSZ        (GPITCH*GPITCH)      // 5184

typedef unsigned long long ull;

// output layout (f32, concatenated flattened tuple)
#define O_NODES 0
#define O_EI    62720
#define O_EF    213248
#define O_BI    439040
#define O_NV    451584
#define O_EV    464128
#define N_EDGE_TOT 75264                // B*196*6

__device__ __align__(16) float g_resp[B * NSCORE];   // 3 MB scratch
__device__ __align__(16) float g_gray[B * GSZ];      // 1.3 MB padded gray
__device__ float2 g_xy [B * MAXN];
__device__ int    g_val[B * MAXN];

__device__ __forceinline__ float score_of(float r) {
    float m = fabsf(r);
    return (m > 0.1f) ? m : -1.0f;
}
__device__ __forceinline__ unsigned enc_f(float s) {
    unsigned b = __float_as_uint(s);
    return (b & 0x80000000u) ? ~b : (b | 0x80000000u);
}

// 4 consecutive outputs (one row) of a KxK SAME conv on the zero-padded gray.
// s_gpad MUST be 16B-aligned: float4 loads at (row*72 + x0)*4 bytes.
template<int K, int PAD, int WOFF>
__device__ __forceinline__ float4 conv_quad(const float* __restrict__ s_gpad,
                                            const float* __restrict__ s_w,
                                            int y, int x0)
{
    float a0 = 0.f, a1 = 0.f, a2 = 0.f, a3 = 0.f;
    #pragma unroll
    for (int dy = 0; dy < K; dy++) {
        const float4* gr4 = reinterpret_cast<const float4*>(
            s_gpad + (y + dy - PAD + 4)*GPITCH + x0);
        float4 q0 = gr4[0], q1 = gr4[1], q2 = gr4[2];
        float gv[12] = {q0.x,q0.y,q0.z,q0.w, q1.x,q1.y,q1.z,q1.w,
                        q2.x,q2.y,q2.z,q2.w};
        const float* wr = s_w + WOFF + dy*K;
        #pragma unroll
        for (int dx = 0; dx < K; dx++) {
            float w = wr[dx];
            const int o = 4 - PAD + dx;
            a0 = fmaf(gv[o],     w, a0);
            a1 = fmaf(gv[o + 1], w, a1);
            a2 = fmaf(gv[o + 2], w, a2);
            a3 = fmaf(gv[o + 3], w, a3);
        }
    }
    return make_float4(a0, a1, a2, a3);
}

// ============================================================
// Kernel 0: crop (bilinear) + gray mean, ONCE per batch.  grid = 64
// Writes zero-padded 72x72 gray to g_gray.
// ============================================================
__global__ void __launch_bounds__(TB)
crop_kernel(const float* __restrict__ img)
{
    __shared__ float s_win[3*WS*WS];

    const int b = blockIdx.x;
    const int t = threadIdx.x;
    const float REC3 = __uint_as_float(0x3EAAAAABu);  // f32(1/3)
    float* gray = g_gray + (size_t)b * GSZ;

    for (int i = t; i < 3*WS*WS; i += TB) {
        int c = i / (WS*WS);
        int r = (i % (WS*WS)) / WS;
        int x = i % WS;
        s_win[i] = img[(((size_t)b*3 + c)*512 + (WB + r))*512 + (WB + x)];
    }
    // zero the whole padded buffer (float4)
    {
        float4* g4 = (float4*)gray;
        for (int i = t; i < GSZ/4; i += TB) g4[i] = make_float4(0,0,0,0);
    }
    __syncthreads();

    #pragma unroll
    for (int g = 0; g < CROP*CROP/TB; g++) {
        int p = g*TB + t;
        int iy = p >> 6, ix = p & 63;
        float bx = __fsub_rn(__fmul_rn((float)ix + 0.5f, 0.03125f), 1.0f);
        float by = __fsub_rn(__fmul_rn((float)iy + 0.5f, 0.03125f), 1.0f);
        float px = __fsub_rn(__fmul_rn(__fadd_rn(__fmul_rn(bx, 0.03125f), 1.0f), 256.0f), 0.5f);
        float py = __fsub_rn(__fmul_rn(__fadd_rn(__fmul_rn(by, 0.03125f), 1.0f), 256.0f), 0.5f);
        int ix0 = (int)floorf(px), iy0 = (int)floorf(py);
        float fx = __fsub_rn(px, (float)ix0);
        float fy = __fsub_rn(py, (float)iy0);
        float wx0 = __fsub_rn(1.0f, fx);
        float wy0 = __fsub_rn(1.0f, fy);
        int lx0 = ix0 - WB, ly0 = iy0 - WB;
        float sum = 0.0f;
        #pragma unroll
        for (int c = 0; c < 3; c++) {
            const float* wc = s_win + c*WS*WS;
            float v00 = wc[ly0*WS + lx0],     v01 = wc[ly0*WS + lx0 + 1];
            float v10 = wc[(ly0+1)*WS + lx0], v11 = wc[(ly0+1)*WS + lx0 + 1];
            float tx0 = __fadd_rn(__fmul_rn(v00, wx0), __fmul_rn(v01, fx));
            float tx1 = __fadd_rn(__fmul_rn(v10, wx0), __fmul_rn(v11, fx));
            float v   = __fadd_rn(__fmul_rn(tx0, wy0), __fmul_rn(tx1, fy));
            sum = __fadd_rn(sum, v);
        }
        gray[(iy + 4)*GPITCH + ix + 4] = __fmul_rn(sum, REC3);
    }
}

// ============================================================
// Kernel 1: DoG conv.  grid = (64, 12) = (batch, ch*4 + quarter)
// Loads padded gray from global (L2-hot), one 4-wide quad per thread.
// ============================================================
__global__ void __launch_bounds__(TB)
conv_kernel(const float* __restrict__ w1,
            const float* __restrict__ w2,
            const float* __restrict__ w3)
{
    __shared__ alignas(16) float s_gpad[GSZ];
    __shared__ float s_w[115];

    const int b  = blockIdx.x;
    const int s  = blockIdx.y;
    const int ch = s >> 2;
    const int q  = s & 3;
    const int t  = threadIdx.x;

    if (t < 9)  s_w[t]      = w1[t];
    if (t < 25) s_w[9 + t]  = w2[t];
    if (t < 81) s_w[34 + t] = w3[t];
    {
        const float4* src = (const float4*)(g_gray + (size_t)b * GSZ);
        float4* dst = (float4*)s_gpad;
        for (int i = t; i < GSZ/4; i += TB) dst[i] = src[i];
    }
    __syncthreads();

    const int y  = q*16 + (t >> 4);
    const int x0 = (t & 15) * 4;
    float4 r;
    if (ch == 0)      r = conv_quad<3, 1, 0 >(s_gpad, s_w, y, x0);
    else if (ch == 1) r = conv_quad<5, 2, 9 >(s_gpad, s_w, y, x0);
    else              r = conv_quad<9, 4, 34>(s_gpad, s_w, y, x0);
    reinterpret_cast<float4*>(g_resp + (size_t)b*NSCORE + ch*4096)[q*256 + t] = r;
}

// smem layout offsets (bytes) for select_kernel (all 16B-aligned)
#define SM_SEL    0        // 256 ull
#define SM_WHIST  2048     // 32*256 u32
#define SM_PART   34816    // 1024 int
#define SM_SCAN   38912    // 385 int
#define SM_WC     40464    // 384 int
#define SM_WS     42000    // 32 int
#define SM_TOTAL  42128

// ============================================================
// Kernel 2: top-k select + sort + node outputs.  grid = 64
// ============================================================
__global__ void __launch_bounds__(TC, 1)
select_kernel(float* __restrict__ out)
{
    extern __shared__ unsigned char dsm[];
    ull*      s_sel   = (ull*)(dsm + SM_SEL);
    unsigned* s_whist = (unsigned*)(dsm + SM_WHIST);
    int*      s_part  = (int*)(dsm + SM_PART);
    int*      s_scan  = (int*)(dsm + SM_SCAN);
    int*      s_wc    = (int*)(dsm + SM_WC);
    int*      s_ws    = (int*)(dsm + SM_WS);
    __shared__ unsigned s_pref;
    __shared__ int s_rem, s_tot;

    const int b = blockIdx.x;
    const int t = threadIdx.x;
    const int lane = t & 31, warp = t >> 5;

    // ---- encode keys straight from global (coalesced, L2-hot) ----
    const float* resp = g_resp + (size_t)b*NSCORE;
    unsigned u[NIT];
    #pragma unroll
    for (int it = 0; it < NIT; it++)
        u[it] = enc_f(score_of(resp[it*TC + t]));
    if (t == 0) { s_pref = 0; s_rem = MAXN; }
    __syncthreads();

    // ---- radix select with early exit, zero atomics ----
    int sh = -1;
    for (int pass = 0; pass < 4; pass++) {
        const int shift = 24 - 8*pass;
        {
            uint4* wz = (uint4*)s_whist;
            wz[t]        = make_uint4(0,0,0,0);
            wz[TC + t]   = make_uint4(0,0,0,0);
        }
        __syncthreads();
        const unsigned pref = s_pref;
        const int rem = s_rem;
        unsigned* wh = s_whist + warp*256;
        #pragma unroll
        for (int it = 0; it < NIT; it++) {
            unsigned uu = u[it];
            bool ok = (pass == 0) || ((uu >> (shift + 8)) == (pref >> (shift + 8)));
            unsigned active = __ballot_sync(0xffffffffu, ok);
            if (ok) {
                unsigned bin = (uu >> shift) & 255u;
                unsigned mset = __match_any_sync(active, bin);
                if (lane == __ffs(mset) - 1)
                    wh[bin] += __popc(mset);
            }
        }
        __syncthreads();
        {
            int bin = t & 255, grp = t >> 8;
            int v = 0;
            #pragma unroll
            for (int w = 0; w < 8; w++)
                v += (int)s_whist[(grp*8 + w)*256 + bin];
            s_part[grp*256 + bin] = v;
        }
        __syncthreads();
        int v = 0;
        if (t < 256) {
            v = s_part[t] + s_part[256 + t] + s_part[512 + t] + s_part[768 + t];
            #pragma unroll
            for (int off = 1; off < 32; off <<= 1) {
                int o = __shfl_down_sync(0xffffffffu, v, off);
                if (lane + off < 32) v += o;
            }
            if (lane == 0) s_ws[warp] = v;
        }
        __syncthreads();
        if (t < 8) {
            int wv = s_ws[t];
            #pragma unroll
            for (int off = 1; off < 8; off <<= 1) {
                int o = __shfl_down_sync(0xFFu, wv, off);
                if (t + off < 8) wv += o;
            }
            s_ws[t] = wv;
        }
        __syncthreads();
        if (t < 256)
            s_scan[t] = v + ((warp < 7) ? s_ws[warp + 1] : 0);   // suffix sums
        __syncthreads();
        if (t < 256) {
            int Sd  = s_scan[t];
            int Sd1 = (t == 255) ? 0 : s_scan[t + 1];
            if (Sd >= rem && Sd1 < rem) {          // unique crossing thread
                s_pref = pref | ((unsigned)t << shift);
                s_rem  = rem - Sd1;
                s_tot  = (MAXN - rem) + Sd;        // all candidates >= boundary
            }
        }
        __syncthreads();
        if (s_tot <= 256) { sh = shift; break; }
    }

    if (sh >= 0) {
        // ---- PATH A: collect all candidates >= truncated boundary, sort ----
        const unsigned th = s_pref >> sh;
        const int tot = s_tot;
        #pragma unroll
        for (int it = 0; it < NIT; it++) {
            unsigned bal = __ballot_sync(0xffffffffu, (u[it] >> sh) >= th);
            if (lane == 0) s_wc[it*NWARP + warp] = __popc(bal);
        }
        __syncthreads();
        if (t < 384) {
            int v = s_wc[t];
            #pragma unroll
            for (int off = 1; off < 32; off <<= 1) {
                int o = __shfl_up_sync(0xffffffffu, v, off);
                if (lane >= off) v += o;
            }
            s_scan[t] = v;
            if (lane == 31) s_ws[warp] = v;
        }
        __syncthreads();
        if (t < 12) {
            int wv = s_ws[t];
            #pragma unroll
            for (int off = 1; off < 16; off <<= 1) {
                int o = __shfl_up_sync(0xFFFu, wv, off);
                if (t >= off) wv += o;
            }
            s_ws[t] = wv;
        }
        __syncthreads();
        #pragma unroll
        for (int it = 0; it < NIT; it++) {
            bool pred = (u[it] >> sh) >= th;
            unsigned bal = __ballot_sync(0xffffffffu, pred);
            int cw = it*NWARP + warp;
            int widx = cw >> 5;
            int excl = s_scan[cw] + ((widx > 0) ? s_ws[widx - 1] : 0) - __popc(bal);
            if (pred) {
                int rank = excl + __popc(bal & ((1u << lane) - 1u));
                s_sel[rank] = (((ull)u[it]) << 32) | (unsigned)(~(unsigned)(it*TC + t));
            }
        }
        if (t >= tot && t < 256) s_sel[t] = 0ULL;
        __syncthreads();
    } else {
        // ---- PATH B (fallback): exact threshold + ordered tie collection ----
        const unsigned u_t = s_pref;
        const int ktie = s_rem;
        #pragma unroll
        for (int it = 0; it < NIT; it++) {
            unsigned bg = __ballot_sync(0xffffffffu, u[it] > u_t);
            unsigned bt = __ballot_sync(0xffffffffu, u[it] == u_t);
            if (lane == 0) s_wc[it*NWARP + warp] = (__popc(bg) << 16) | __popc(bt);
        }
        __syncthreads();
        if (t < 384) {
            int v = s_wc[t];
            #pragma unroll
            for (int off = 1; off < 32; off <<= 1) {
                int o = __shfl_up_sync(0xffffffffu, v, off);
                if (lane >= off) v += o;
            }
            s_scan[t] = v;
            if (lane == 31) s_ws[warp] = v;
        }
        __syncthreads();
        if (t < 12) {
            int wv = s_ws[t];
            #pragma unroll
            for (int off = 1; off < 16; off <<= 1) {
                int o = __shfl_up_sync(0xFFFu, wv, off);
                if (t >= off) wv += o;
            }
            s_ws[t] = wv;
        }
        __syncthreads();
        const int cG = s_ws[11] >> 16;
        #pragma unroll
        for (int it = 0; it < NIT; it++) {
            unsigned uu = u[it];
            bool g = (uu > u_t), e = (uu == u_t);
            unsigned bg = __ballot_sync(0xffffffffu, g);
            unsigned bt = __ballot_sync(0xffffffffu, e);
            int cw = it*NWARP + warp;
            int widx = cw >> 5;
            int incl = s_scan[cw] + ((widx > 0) ? s_ws[widx - 1] : 0);
            int excl = incl - ((__popc(bg) << 16) | __popc(bt));
            unsigned below = (1u << lane) - 1u;
            if (g) {
                int rank = (excl >> 16) + __popc(bg & below);
                s_sel[rank] = (((ull)uu) << 32) | (unsigned)(~(unsigned)(it*TC + t));
            }
            if (e) {
                int rank = (excl & 0xFFFF) + __popc(bt & below);
                if (rank < ktie)
                    s_sel[cG + rank] = (((ull)u_t) << 32) | (unsigned)(~(unsigned)(it*TC + t));
            }
        }
        if (t >= MAXN && t < 256) s_sel[t] = 0ULL;
        __syncthreads();
    }

    // ---- bitonic sort 256 keys descending (value desc, index asc) ----
    ull k = (t < 256) ? s_sel[t] : 0ULL;
    if (t < 256) {
        #pragma unroll
        for (int kk = 2; kk <= 32; kk <<= 1) {
            #pragma unroll
            for (int j = kk >> 1; j > 0; j >>= 1) {
                ull o = __shfl_xor_sync(0xffffffffu, k, j);
                bool takeMax = (((t & kk) == 0) != ((t & j) != 0));
                k = takeMax ? (k > o ? k : o) : (k < o ? k : o);
            }
        }
    }
    #pragma unroll
    for (int kk = 64; kk <= 256; kk <<= 1) {
        for (int j = kk >> 1; j >= 32; j >>= 1) {
            __syncthreads();
            if (t < 256) s_sel[t] = k;
            __syncthreads();
            if (t < 256) {
                ull o = s_sel[t ^ j];
                bool takeMax = (((t & kk) == 0) != ((t & j) != 0));
                k = takeMax ? (k > o ? k : o) : (k < o ? k : o);
            }
        }
        if (t < 256) {
            #pragma unroll
            for (int j = 16; j > 0; j >>= 1) {
                ull o = __shfl_xor_sync(0xffffffffu, k, j);
                bool takeMax = (((t & kk) == 0) != ((t & j) != 0));
                k = takeMax ? (k > o ? k : o) : (k < o ? k : o);
            }
        }
    }

    // ---- node features + export (x, y, valid) for the NN kernel ----
    const float REC63x2 = __uint_as_float(0x3D020821u);  // f32(1/63)*2
    if (t < MAXN) {
        unsigned idx = ~((unsigned)k);
        float rv = resp[idx];
        bool valid = (fabsf(rv) > 0.1f);
        int c  = idx >> 12;
        int rem2 = idx & 4095;
        int yi = rem2 >> 6, xi = rem2 & 63;
        float xc = __fsub_rn(__fmul_rn((float)xi, REC63x2), 1.0f);
        float yc = __fsub_rn(__fmul_rn((float)yi, REC63x2), 1.0f);
        float ecc = __fsqrt_rn(__fadd_rn(__fmul_rn(xc, xc), __fmul_rn(yc, yc)));
        float pol = (rv > 0.0f) ? 1.0f : ((rv < 0.0f) ? -1.0f : 0.0f);
        float vf = valid ? 1.0f : 0.0f;
        float* nrow = out + O_NODES + ((size_t)b*MAXN + t)*5;
        nrow[0] = xc * vf;
        nrow[1] = yc * vf;
        nrow[2] = pol * vf;
        nrow[3] = (float)c * vf;
        nrow[4] = ecc * vf;
        g_xy [b*MAXN + t] = make_float2(xc * vf, yc * vf);
        g_val[b*MAXN + t] = valid ? 1 : 0;
        out[O_NV + b*MAXN + t] = vf;
        out[O_BI + b*MAXN + t] = (float)b;
    }
}

// ============================================================
// Kernel 3: 6-NN + edges, one warp per node.  grid = (64, 13), 512 thr
// ============================================================
__global__ void __launch_bounds__(TN)
nn_kernel(float* __restrict__ out)
{
    __shared__ float2 s_xy[MAXN];
    __shared__ int s_val[MAXN];

    const int b = blockIdx.x;
    const int t = threadIdx.x;
    const int lane = t & 31, warp = t >> 5;

    if (t < MAXN) {
        int v = g_val[b*MAXN + t];
        float2 xy = g_xy[b*MAXN + t];
        s_val[t] = v;
        // sentinel coords for invalid nodes: distance becomes inf, sorts after
        // all real distances (like the reference's 1e9); those slots only ever
        // emit ev=0 -> all-zero outputs.
        s_xy[t] = v ? xy : make_float2(1e19f, 1e19f);
    }
    __syncthreads();

    const int node = blockIdx.y * (TN/32) + warp;
    if (node >= MAXN) return;

    const float2 p = s_xy[node];
    const int sv = s_val[node];

    // collect 7 raw keys; m=0..5 always in-range (lane+160 <= 191 < 196)
    ull key[7];
    #pragma unroll
    for (int m = 0; m < 6; m++) {
        int j = lane + m*32;
        float2 pj = s_xy[j];
        float dx = __fsub_rn(p.x, pj.x);
        float dy = __fsub_rn(p.y, pj.y);
        float s2 = __fadd_rn(__fmul_rn(dx, dx), __fmul_rn(dy, dy));
        float d = (s2 > 0.0f) ? __fsqrt_rn(s2) : 0.0f;
        if (j == node) d = 1000000000.0f;
        key[m] = (((ull)__float_as_uint(d)) << 32) | (unsigned)j;
    }
    {
        int j = lane + 192;
        if (j < MAXN) {
            float2 pj = s_xy[j];
            float dx = __fsub_rn(p.x, pj.x);
            float dy = __fsub_rn(p.y, pj.y);
            float s2 = __fadd_rn(__fmul_rn(dx, dx), __fmul_rn(dy, dy));
            float d = (s2 > 0.0f) ? __fsqrt_rn(s2) : 0.0f;
            if (j == node) d = 1000000000.0f;
            key[6] = (((ull)__float_as_uint(d)) << 32) | (unsigned)j;
        } else {
            key[6] = 0xFFFFFFFF00000000ULL;   // sorts after everything real
        }
    }

    // odd-even transposition sort of 7 keys (21 CAS)
    #pragma unroll
    for (int r = 0; r < 7; r++) {
        #pragma unroll
        for (int i = (r & 1); i + 1 < 7; i += 2) {
            ull a = key[i], c = key[i+1];
            key[i]   = (a < c) ? a : c;
            key[i+1] = (a < c) ? c : a;
        }
    }

    // 6-round tournament, 32-bit reductions (d >= 0 -> bits monotone unsigned)
    unsigned res_d = 0xFFFFFFFFu, res_j = 0;
    #pragma unroll
    for (int q = 0; q < KNBR; q++) {
        unsigned dh = (unsigned)(key[0] >> 32);
        unsigned jh = (unsigned)key[0];
        unsigned dmin = dh;
        #pragma unroll
        for (int off = 16; off > 0; off >>= 1) {
            unsigned o = __shfl_xor_sync(0xffffffffu, dmin, off);
            dmin = (o < dmin) ? o : dmin;
        }
        unsigned jm = (dh == dmin) ? jh : 0xFFFFFFFFu;
        #pragma unroll
        for (int off = 16; off > 0; off >>= 1) {
            unsigned o = __shfl_xor_sync(0xffffffffu, jm, off);
            jm = (o < jm) ? o : jm;
        }
        if (lane == q) { res_d = dmin; res_j = jm; }
        if (dh == dmin && jh == jm) {
            #pragma unroll
            for (int r = 0; r < 6; r++) key[r] = key[r+1];
            key[6] = 0xFFFFFFFFFFFFFFFFULL;
        }
    }

    // lanes 0..5 emit edges (select-masked: sentinel values never leak)
    if (lane < KNBR) {
        const float DIST_T = (float)(4.05 / 4.2);
        unsigned jd = res_j;
        float d = __uint_as_float(res_d);
        bool ev = (d < DIST_T) && (sv != 0);
        float2 pj = s_xy[jd];
        float dx = __fsub_rn(pj.x, p.x);
        float dy = __fsub_rn(pj.y, p.y);
        float s2 = __fadd_rn(__fmul_rn(dx, dx), __fmul_rn(dy, dy));
        float cd = (s2 > 0.0f) ? __fsqrt_rn(s2) : 0.0f;
        size_t e = ((size_t)b*MAXN + node)*KNBR + lane;
        out[O_EI + e]              = ev ? (float)(b*MAXN + node) : 0.0f;
        out[O_EI + N_EDGE_TOT + e] = ev ? (float)(b*MAXN + jd)   : 0.0f;
        out[O_EF + e*3 + 0] = ev ? dx : 0.0f;
        out[O_EF + e*3 + 1] = ev ? dy : 0.0f;
        out[O_EF + e*3 + 2] = ev ? cd : 0.0f;
        out[O_EV + e] = ev ? 1.0f : 0.0f;
    }
}

extern "C" void kernel_launch(void* const* d_in, const int* in_sizes, int n_in,
                              void* d_out, int out_size)
{
    const float* img = (const float*)d_in[0];
    const float* w1  = (const float*)d_in[1];
    const float* w2  = (const float*)d_in[2];
    const float* w3  = (const float*)d_in[3];
    float* out = (float*)d_out;

    crop_kernel<<<B, TB>>>(img);
    conv_kernel<<<dim3(B, 12), TB>>>(w1, w2, w3);

    cudaFuncSetAttribute(select_kernel,
                         cudaFuncAttributeMaxDynamicSharedMemorySize, SM_TOTAL);
    select_kernel<<<B, TC, SM_TOTAL>>>(out);

    nn_kernel<<<dim3(B, (MAXN + TN/32 - 1) / (TN/32)), TN>>>(out);
}